// round 2
// baseline (speedup 1.0000x reference)
#include <cuda_runtime.h>

// Problem constants
#define PB 4
#define PS 2048
#define PE 1024
#define PH 16
#define PD 64
#define PM (PB * PS)   // 8192

// Scratch (device globals: allocation-free)
__device__ float g_Q[PB * PH * PS * PD];
__device__ float g_K[PB * PH * PS * PD];
__device__ float g_V[PB * PH * PS * PD];
__device__ float g_Ctx[PB * PS * PE];

// ---------------------------------------------------------------------------
// GEMM (NT): C[m,n] = sum_k A[m,k] * W[n,k],  M=8192, N=1024, K=1024
// 128x128 tile, BK=16, 256 threads, 8x8 per thread, float4 smem reads.
// DST: 0->g_Q, 1->g_K, 2->g_V, 3->Cparam (plain row-major)
// SRCCTX: use g_Ctx as A
// DST<3 scatters C[m,n] into [b,h,s,d] layout.
// ---------------------------------------------------------------------------
template <int DST, bool SRCCTX>
__global__ __launch_bounds__(256) void gemm_nt_kernel(
    const float* __restrict__ Aparam,
    const float* __restrict__ W,
    float* __restrict__ Cparam)
{
    constexpr int K = PE;
    constexpr int N = PE;
    __shared__ float As[16][132];
    __shared__ float Ws[16][132];

    const float* A = SRCCTX ? (const float*)g_Ctx : Aparam;

    const int tid = threadIdx.x;
    const int bm = blockIdx.y;
    const int bn = blockIdx.x;
    const int tx = tid & 15;
    const int ty = tid >> 4;

    float acc[8][8];
#pragma unroll
    for (int i = 0; i < 8; i++)
#pragma unroll
        for (int j = 0; j < 8; j++) acc[i][j] = 0.0f;

    for (int kt = 0; kt < K; kt += 16) {
#pragma unroll
        for (int it = 0; it < 2; it++) {
            int f = tid + it * 256;            // 0..511 float4 slots
            int row = f >> 2;                  // 0..127
            int q = (f & 3) * 4;               // 0,4,8,12
            float4 av = *(const float4*)&A[(size_t)(bm * 128 + row) * K + kt + q];
            As[q + 0][row] = av.x; As[q + 1][row] = av.y;
            As[q + 2][row] = av.z; As[q + 3][row] = av.w;
            float4 wv = *(const float4*)&W[(size_t)(bn * 128 + row) * K + kt + q];
            Ws[q + 0][row] = wv.x; Ws[q + 1][row] = wv.y;
            Ws[q + 2][row] = wv.z; Ws[q + 3][row] = wv.w;
        }
        __syncthreads();

#pragma unroll
        for (int kk = 0; kk < 16; kk++) {
            float a[8], b[8];
            *(float4*)&a[0] = *(const float4*)&As[kk][ty * 8];
            *(float4*)&a[4] = *(const float4*)&As[kk][ty * 8 + 4];
            *(float4*)&b[0] = *(const float4*)&Ws[kk][tx * 8];
            *(float4*)&b[4] = *(const float4*)&Ws[kk][tx * 8 + 4];
#pragma unroll
            for (int i = 0; i < 8; i++)
#pragma unroll
                for (int j = 0; j < 8; j++)
                    acc[i][j] += a[i] * b[j];
        }
        __syncthreads();
    }

    // Epilogue
    if (DST < 3) {
        float* C = (DST == 0) ? g_Q : (DST == 1) ? g_K : g_V;
#pragma unroll
        for (int i = 0; i < 8; i++) {
            int m = bm * 128 + ty * 8 + i;
            int bb = m >> 11;          // / PS
            int s = m & (PS - 1);
#pragma unroll
            for (int jv = 0; jv < 2; jv++) {
                int n = bn * 128 + tx * 8 + jv * 4;
                int h = n >> 6;
                int d = n & 63;
                float4 v = make_float4(acc[i][jv * 4 + 0], acc[i][jv * 4 + 1],
                                       acc[i][jv * 4 + 2], acc[i][jv * 4 + 3]);
                *(float4*)&C[((size_t)(bb * PH + h) * PS + s) * PD + d] = v;
            }
        }
    } else {
#pragma unroll
        for (int i = 0; i < 8; i++) {
            int m = bm * 128 + ty * 8 + i;
#pragma unroll
            for (int jv = 0; jv < 2; jv++) {
                int n = bn * 128 + tx * 8 + jv * 4;
                float4 v = make_float4(acc[i][jv * 4 + 0], acc[i][jv * 4 + 1],
                                       acc[i][jv * 4 + 2], acc[i][jv * 4 + 3]);
                *(float4*)&Cparam[(size_t)m * N + n] = v;
            }
        }
    }
}

// ---------------------------------------------------------------------------
// Flash attention: per block (q-tile of 64, head, batch). 256 threads.
// Smem: Qs[64x64] + KPs[64x64] (K transposed, later reused for P) + Vs[64x64]
//       = exactly 48 KB.
// Thread (ty,tx) owns rows 4*ty+i, cols 4*tx+j (4x4).
// Writes context * gamma into g_Ctx in [b, s, h*D+d] layout.
// ---------------------------------------------------------------------------
__global__ __launch_bounds__(256) void attn_kernel(
    const unsigned char* __restrict__ mask,
    const float* __restrict__ gamma)
{
    __shared__ float Qs[64 * 64];
    __shared__ float KPs[64 * 64];
    __shared__ float Vs[64 * 64];

    const int tid = threadIdx.x;
    const int qt = blockIdx.x;
    const int h  = blockIdx.y;
    const int b  = blockIdx.z;
    const int tx = tid & 15;
    const int ty = tid >> 4;

    const size_t headBase = (size_t)(b * PH + h) * PS * PD;
    const float* Qg = g_Q + headBase + (size_t)qt * 64 * PD;

#pragma unroll
    for (int it = 0; it < 4; it++) {
        int f = tid + it * 256;
        ((float4*)Qs)[f] = ((const float4*)Qg)[f];
    }

    float m_i[4], l_i[4], o[4][4];
#pragma unroll
    for (int i = 0; i < 4; i++) {
        m_i[i] = -3.0e38f;
        l_i[i] = 0.0f;
#pragma unroll
        for (int j = 0; j < 4; j++) o[i][j] = 0.0f;
    }

    const unsigned char* mrow = mask + (size_t)b * PS;

    for (int kt = 0; kt < PS / 64; kt++) {
        const float* Kg = g_K + headBase + (size_t)kt * 64 * PD;
        const float* Vg = g_V + headBase + (size_t)kt * 64 * PD;

        __syncthreads();  // previous iteration done with KPs/Vs (and Q visible on iter 0 path)
#pragma unroll
        for (int it = 0; it < 4; it++) {
            int f = tid + it * 256;
            int kk = f >> 4;
            int dq = (f & 15) * 4;
            float4 kv = ((const float4*)Kg)[f];
            KPs[(dq + 0) * 64 + kk] = kv.x;
            KPs[(dq + 1) * 64 + kk] = kv.y;
            KPs[(dq + 2) * 64 + kk] = kv.z;
            KPs[(dq + 3) * 64 + kk] = kv.w;
            ((float4*)Vs)[f] = ((const float4*)Vg)[f];
        }
        __syncthreads();

        // scores S = Q Kt  (64x64x64)
        float s[4][4];
#pragma unroll
        for (int i = 0; i < 4; i++)
#pragma unroll
            for (int j = 0; j < 4; j++) s[i][j] = 0.0f;

#pragma unroll 8
        for (int d = 0; d < 64; d++) {
            float a0 = Qs[(ty * 4 + 0) * 64 + d];
            float a1 = Qs[(ty * 4 + 1) * 64 + d];
            float a2 = Qs[(ty * 4 + 2) * 64 + d];
            float a3 = Qs[(ty * 4 + 3) * 64 + d];
            float4 bv = *(const float4*)&KPs[d * 64 + tx * 4];
            s[0][0] += a0 * bv.x; s[0][1] += a0 * bv.y; s[0][2] += a0 * bv.z; s[0][3] += a0 * bv.w;
            s[1][0] += a1 * bv.x; s[1][1] += a1 * bv.y; s[1][2] += a1 * bv.z; s[1][3] += a1 * bv.w;
            s[2][0] += a2 * bv.x; s[2][1] += a2 * bv.y; s[2][2] += a2 * bv.z; s[2][3] += a2 * bv.w;
            s[3][0] += a3 * bv.x; s[3][1] += a3 * bv.y; s[3][2] += a3 * bv.z; s[3][3] += a3 * bv.w;
        }

        // scale + padding mask
        uchar4 mv = *(const uchar4*)&mrow[kt * 64 + tx * 4];
        float mb[4];
        mb[0] = mv.x ? 1.0f : 0.0f;
        mb[1] = mv.y ? 1.0f : 0.0f;
        mb[2] = mv.z ? 1.0f : 0.0f;
        mb[3] = mv.w ? 1.0f : 0.0f;
#pragma unroll
        for (int i = 0; i < 4; i++)
#pragma unroll
            for (int j = 0; j < 4; j++) {
                float v = s[i][j] * 0.125f;   // 1/sqrt(64)
                s[i][j] = (mb[j] != 0.0f) ? -3.0e38f : v;
            }

        // online softmax (rows reduced across 16 lanes)
        float tm[4];
#pragma unroll
        for (int i = 0; i < 4; i++) {
            tm[i] = fmaxf(fmaxf(s[i][0], s[i][1]), fmaxf(s[i][2], s[i][3]));
#pragma unroll
            for (int off = 8; off >= 1; off >>= 1)
                tm[i] = fmaxf(tm[i], __shfl_xor_sync(0xffffffffu, tm[i], off, 16));
        }

        float p[4][4], rs[4], csc[4];
#pragma unroll
        for (int i = 0; i < 4; i++) {
            float mn = fmaxf(m_i[i], tm[i]);
            csc[i] = __expf(m_i[i] - mn);
            m_i[i] = mn;
            float acc = 0.0f;
#pragma unroll
            for (int j = 0; j < 4; j++) {
                p[i][j] = __expf(s[i][j] - mn);
                acc += p[i][j];
            }
            rs[i] = acc;
#pragma unroll
            for (int off = 8; off >= 1; off >>= 1)
                rs[i] += __shfl_xor_sync(0xffffffffu, rs[i], off, 16);
            l_i[i] = l_i[i] * csc[i] + rs[i];
#pragma unroll
            for (int j = 0; j < 4; j++) o[i][j] *= csc[i];
        }

        __syncthreads();  // all threads done reading KPs as K
#pragma unroll
        for (int i = 0; i < 4; i++)
            *(float4*)&KPs[(ty * 4 + i) * 64 + tx * 4] =
                make_float4(p[i][0], p[i][1], p[i][2], p[i][3]);
        __syncthreads();

        // O += P V  (64x64x64)
#pragma unroll 8
        for (int k = 0; k < 64; k++) {
            float p0 = KPs[(ty * 4 + 0) * 64 + k];
            float p1 = KPs[(ty * 4 + 1) * 64 + k];
            float p2 = KPs[(ty * 4 + 2) * 64 + k];
            float p3 = KPs[(ty * 4 + 3) * 64 + k];
            float4 vv = *(const float4*)&Vs[k * 64 + tx * 4];
            o[0][0] += p0 * vv.x; o[0][1] += p0 * vv.y; o[0][2] += p0 * vv.z; o[0][3] += p0 * vv.w;
            o[1][0] += p1 * vv.x; o[1][1] += p1 * vv.y; o[1][2] += p1 * vv.z; o[1][3] += p1 * vv.w;
            o[2][0] += p2 * vv.x; o[2][1] += p2 * vv.y; o[2][2] += p2 * vv.z; o[2][3] += p2 * vv.w;
            o[3][0] += p3 * vv.x; o[3][1] += p3 * vv.y; o[3][2] += p3 * vv.z; o[3][3] += p3 * vv.w;
        }
    }

    const float gsc = gamma[h];
    float* Og = g_Ctx + ((size_t)b * PS + (size_t)qt * 64) * PE + h * PD;
#pragma unroll
    for (int i = 0; i < 4; i++) {
        float inv = gsc / l_i[i];
        float4 ov = make_float4(o[i][0] * inv, o[i][1] * inv,
                                o[i][2] * inv, o[i][3] * inv);
        *(float4*)&Og[(size_t)(ty * 4 + i) * PE + tx * 4] = ov;
    }
}

// ---------------------------------------------------------------------------
extern "C" void kernel_launch(void* const* d_in, const int* in_sizes, int n_in,
                              void* d_out, int out_size)
{
    const float* query = (const float*)d_in[0];
    const float* key   = (const float*)d_in[1];
    const float* value = (const float*)d_in[2];
    const unsigned char* mask = (const unsigned char*)d_in[3];
    const float* Wq = (const float*)d_in[4];
    const float* Wk = (const float*)d_in[5];
    const float* Wv = (const float*)d_in[6];
    const float* Wo = (const float*)d_in[7];
    const float* gamma = (const float*)d_in[8];

    dim3 gp(PE / 128, PM / 128);   // (8, 64)
    gemm_nt_kernel<0, false><<<gp, 256>>>(query, Wq, nullptr);
    gemm_nt_kernel<1, false><<<gp, 256>>>(key, Wk, nullptr);
    gemm_nt_kernel<2, false><<<gp, 256>>>(value, Wv, nullptr);

    attn_kernel<<<dim3(PS / 64, PH, PB), 256>>>(mask, gamma);

    gemm_nt_kernel<3, true><<<gp, 256>>>(nullptr, Wo, (float*)d_out);
}